// round 13
// baseline (speedup 1.0000x reference)
#include <cuda_runtime.h>
#include <math.h>

#define HID   1024
#define BSZ   16
#define NOPT  4
#define ROWS  (BSZ*NOPT)    // 64
#define TRUN  2
#define SEQ   1536
#define PLEN  512
#define QLEN  128

#define RPG   8              // rows per row-group (one cluster)
#define CT    8              // col-tiles (cluster size)
#define CTILE 128            // cols per CTA
#define NCTA  ((ROWS/RPG)*CT)   // 64 CTAs

// smem layout (dynamic): As2[8][1024] float2 dup (64KB) | Rbuf[128][4] u64 (4KB) | larr[8]
#define SMEM_AS2   0
#define SMEM_RBUF  65536
#define SMEM_LARR  (65536 + 4096)
#define SMEM_BYTES (65536 + 4096 + 64)

// Scratch (device globals — no allocation allowed)
__device__ float g_feats[ROWS*HID];
__device__ float g_h1[ROWS*HID];
__device__ float g_logits[ROWS];

// ---------------------------------------------------------------------------
// f32x2 helpers
// ---------------------------------------------------------------------------
__device__ __forceinline__ void fma_f32x2(unsigned long long& acc,
                                          unsigned long long a,
                                          unsigned long long b) {
    asm("fma.rn.f32x2 %0, %1, %2, %0;" : "+l"(acc) : "l"(a), "l"(b));
}
__device__ __forceinline__ unsigned long long add_f32x2(unsigned long long a,
                                                        unsigned long long b) {
    unsigned long long r;
    asm("add.rn.f32x2 %0, %1, %2;" : "=l"(r) : "l"(a), "l"(b));
    return r;
}
__device__ __forceinline__ float lo_f(unsigned long long v) {
    return __uint_as_float((unsigned)(v & 0xFFFFFFFFull));
}
__device__ __forceinline__ float hi_f(unsigned long long v) {
    return __uint_as_float((unsigned)(v >> 32));
}
__device__ __forceinline__ long long opt_at(const void* p, bool is64, int i) {
    if (is64) return ((const long long*)p)[i];
    return (long long)((const int*)p)[i];
}
__device__ __forceinline__ void cluster_sync_() {
    asm volatile("barrier.cluster.arrive.aligned;" ::: "memory");
    asm volatile("barrier.cluster.wait.aligned;"   ::: "memory");
}

// Shared full-K GEMM core: acc for 2 rows x 4 cols over this thread's k-half.
// As2 must hold duplicated (a,a) pairs [row][k]. Returns 4 packed accumulators.
__device__ __forceinline__ void gemm_core(const float* __restrict__ W,
                                          const float2 (*As2)[HID],
                                          unsigned long long (*Rbuf)[4],
                                          int c0, int rl, int klane,
                                          unsigned long long acc[4]) {
    const int tid = threadIdx.x;
    const float* Wp = W + (size_t)(klane * 512) * HID + c0;
    const unsigned long long* a0p =
        (const unsigned long long*)&As2[rl * 2 + 0][klane * 512];
    const unsigned long long* a1p =
        (const unsigned long long*)&As2[rl * 2 + 1][klane * 512];

    acc[0] = acc[1] = acc[2] = acc[3] = 0ull;
    #pragma unroll 4
    for (int kk = 0; kk < 512; kk++) {
        ulonglong2 w = *(const ulonglong2*)(Wp + (size_t)kk * HID);
        unsigned long long a0 = a0p[kk];
        unsigned long long a1 = a1p[kk];
        fma_f32x2(acc[0], a0, w.x); fma_f32x2(acc[1], a0, w.y);
        fma_f32x2(acc[2], a1, w.x); fma_f32x2(acc[3], a1, w.y);
    }
    // k-halves reduce via smem
    if (klane) {
        Rbuf[tid - 128][0] = acc[0]; Rbuf[tid - 128][1] = acc[1];
        Rbuf[tid - 128][2] = acc[2]; Rbuf[tid - 128][3] = acc[3];
    }
    __syncthreads();
    if (!klane) {
        acc[0] = add_f32x2(acc[0], Rbuf[tid][0]);
        acc[1] = add_f32x2(acc[1], Rbuf[tid][1]);
        acc[2] = add_f32x2(acc[2], Rbuf[tid][2]);
        acc[3] = add_f32x2(acc[3], Rbuf[tid][3]);
    }
}

// ---------------------------------------------------------------------------
// NODE 1: feats (cluster-cooperative) + full-K GEMM1, h1 = relu(b1 + feats@W1)
// ---------------------------------------------------------------------------
__global__ void __launch_bounds__(256) __cluster_dims__(CT, 1, 1)
layer1_kernel(const float* __restrict__ emb, const void* __restrict__ opt_length,
              const float* __restrict__ b1, const float* __restrict__ W1,
              float* __restrict__ out, int out_size) {
    extern __shared__ char smem_raw[];
    float2 (*As2)[HID] = reinterpret_cast<float2(*)[HID]>(smem_raw + SMEM_AS2);
    unsigned long long (*Rbuf)[4] =
        reinterpret_cast<unsigned long long(*)[4]>(smem_raw + SMEM_RBUF);

    const int rg  = blockIdx.x >> 3;     // row-group 0..7 (cluster id)
    const int ct  = blockIdx.x & 7;      // col-tile = cluster rank
    const int tid = threadIdx.x;

    // CTA 0 zeroes logits + loss slot (ordered before node2 by graph)
    if (blockIdx.x == 0) {
        if (tid < ROWS) g_logits[tid] = 0.f;
        if (tid == ROWS) {
            if (out_size == 1)             out[0] = 0.f;
            else if (out_size >= ROWS + 1) out[ROWS] = 0.f;
        }
    }

    // --- feats: rank ct computes row rg*8+ct into global ---
    {
        int row = rg * RPG + ct;
        int b = row >> 2, o = row & 3;
        bool is64 = (((const int*)opt_length)[1] == 0);
        long long cs = 0;
        for (int i = 0; i <= o; i++) cs += opt_at(opt_length, is64, i);
        int ohead = PLEN + QLEN + (int)cs;
        int otail = ohead + (int)opt_at(opt_length, is64, o + 1) - 1;
        int pos[6] = {0, PLEN - 1, PLEN, PLEN + QLEN - 1, ohead, otail};

        int c4 = tid * 4;
        float4 acc = make_float4(0.f, 0.f, 0.f, 0.f);
        #pragma unroll
        for (int t = 0; t < TRUN; t++) {
            const float* base = emb + (size_t)(t * BSZ + b) * SEQ * HID;
            #pragma unroll
            for (int p = 0; p < 6; p++) {
                float4 v = *(const float4*)(base + (size_t)pos[p] * HID + c4);
                acc.x += v.x; acc.y += v.y; acc.z += v.z; acc.w += v.w;
            }
        }
        const float s = 0.25f;
        *(float4*)(g_feats + (size_t)row * HID + c4) =
            make_float4(acc.x * s, acc.y * s, acc.z * s, acc.w * s);
    }
    __threadfence();
    cluster_sync_();

    // --- load all 8 rows into duplicated smem ---
    {
        int c4 = tid * 4;
        #pragma unroll
        for (int r = 0; r < RPG; r++) {
            float4 v = __ldcg((const float4*)(g_feats +
                              (size_t)(rg * RPG + r) * HID + c4));
            *(float4*)&As2[r][c4 + 0] = make_float4(v.x, v.x, v.y, v.y);
            *(float4*)&As2[r][c4 + 2] = make_float4(v.z, v.z, v.w, v.w);
        }
    }
    __syncthreads();

    const int collane = tid & 31;
    const int rl      = (tid >> 5) & 3;
    const int klane   = tid >> 7;
    const int c0      = ct * CTILE + collane * 4;

    unsigned long long acc[4];
    gemm_core(W1, As2, Rbuf, c0, rl, klane, acc);

    if (!klane) {
        float4 bv = *(const float4*)(b1 + c0);
        int row0 = rg * RPG + rl * 2;
        float4 v0 = make_float4(fmaxf(lo_f(acc[0]) + bv.x, 0.f),
                                fmaxf(hi_f(acc[0]) + bv.y, 0.f),
                                fmaxf(lo_f(acc[1]) + bv.z, 0.f),
                                fmaxf(hi_f(acc[1]) + bv.w, 0.f));
        float4 v1 = make_float4(fmaxf(lo_f(acc[2]) + bv.x, 0.f),
                                fmaxf(hi_f(acc[2]) + bv.y, 0.f),
                                fmaxf(lo_f(acc[3]) + bv.z, 0.f),
                                fmaxf(hi_f(acc[3]) + bv.w, 0.f));
        *(float4*)(g_h1 + (size_t)row0 * HID + c0)       = v0;
        *(float4*)(g_h1 + (size_t)(row0 + 1) * HID + c0) = v1;
    }
}

// ---------------------------------------------------------------------------
// NODE 2: full-K GEMM2 (h2 = b2 + h1@W2 internal) + fused relu·W3 gemv
//         partials red.added to g_logits; cluster.sync; rank0 writes logits
//         and its 2 batches' loss contribution.
// ---------------------------------------------------------------------------
__global__ void __launch_bounds__(256) __cluster_dims__(CT, 1, 1)
layer2_kernel(const float* __restrict__ W2, const float* __restrict__ b2,
              const float* __restrict__ W3, const int* __restrict__ y,
              float* __restrict__ out, int out_size) {
    extern __shared__ char smem_raw[];
    float2 (*As2)[HID] = reinterpret_cast<float2(*)[HID]>(smem_raw + SMEM_AS2);
    unsigned long long (*Rbuf)[4] =
        reinterpret_cast<unsigned long long(*)[4]>(smem_raw + SMEM_RBUF);
    float* larr = reinterpret_cast<float*>(smem_raw + SMEM_LARR);

    const int rg  = blockIdx.x >> 3;
    const int ct  = blockIdx.x & 7;
    const int tid = threadIdx.x;

    // load h1 rows (already relu'd) into duplicated smem
    {
        int c4 = tid * 4;
        #pragma unroll
        for (int r = 0; r < RPG; r++) {
            float4 v = __ldcg((const float4*)(g_h1 +
                              (size_t)(rg * RPG + r) * HID + c4));
            *(float4*)&As2[r][c4 + 0] = make_float4(v.x, v.x, v.y, v.y);
            *(float4*)&As2[r][c4 + 2] = make_float4(v.z, v.z, v.w, v.w);
        }
    }
    __syncthreads();

    const int collane = tid & 31;
    const int rl      = (tid >> 5) & 3;
    const int klane   = tid >> 7;
    const int c0      = ct * CTILE + collane * 4;

    unsigned long long acc[4];
    gemm_core(W2, As2, Rbuf, c0, rl, klane, acc);

    if (!klane) {
        float4 bv = *(const float4*)(b2 + c0);
        float4 wv = *(const float4*)(W3 + c0);
        float p0 = fmaxf(lo_f(acc[0]) + bv.x, 0.f) * wv.x
                 + fmaxf(hi_f(acc[0]) + bv.y, 0.f) * wv.y
                 + fmaxf(lo_f(acc[1]) + bv.z, 0.f) * wv.z
                 + fmaxf(hi_f(acc[1]) + bv.w, 0.f) * wv.w;
        float p1 = fmaxf(lo_f(acc[2]) + bv.x, 0.f) * wv.x
                 + fmaxf(hi_f(acc[2]) + bv.y, 0.f) * wv.y
                 + fmaxf(lo_f(acc[3]) + bv.z, 0.f) * wv.z
                 + fmaxf(hi_f(acc[3]) + bv.w, 0.f) * wv.w;
        #pragma unroll
        for (int off = 16; off; off >>= 1) {
            p0 += __shfl_down_sync(0xFFFFFFFFu, p0, off);
            p1 += __shfl_down_sync(0xFFFFFFFFu, p1, off);
        }
        if (collane == 0) {
            int row0 = rg * RPG + rl * 2;
            asm volatile("red.global.add.f32 [%0], %1;"
                         :: "l"(g_logits + row0), "f"(p0) : "memory");
            asm volatile("red.global.add.f32 [%0], %1;"
                         :: "l"(g_logits + row0 + 1), "f"(p1) : "memory");
        }
    }
    __threadfence();
    cluster_sync_();

    if (ct == 0) {
        if (tid < RPG) larr[tid] = __ldcg(&g_logits[rg * RPG + tid]);
        __syncthreads();
        if (tid < RPG && out_size >= ROWS) out[rg * RPG + tid] = larr[tid];
        if (tid == 0) {
            float lsum = 0.f;
            #pragma unroll
            for (int bb = 0; bb < 2; bb++) {
                int batch = rg * 2 + bb;
                float l0 = larr[bb * 4 + 0], l1 = larr[bb * 4 + 1];
                float l2 = larr[bb * 4 + 2], l3 = larr[bb * 4 + 3];
                float m  = fmaxf(fmaxf(l0, l1), fmaxf(l2, l3));
                float se = expf(l0 - m) + expf(l1 - m)
                         + expf(l2 - m) + expf(l3 - m);
                float lse = m + logf(se);
                int yy = y[batch];
                float ly = (yy == 0) ? l0 : (yy == 1) ? l1 : (yy == 2) ? l2 : l3;
                lsum += -(ly - lse);
            }
            float contrib = lsum * (1.0f / (float)BSZ);
            float* dst = (out_size == 1) ? out
                       : (out_size >= ROWS + 1) ? (out + ROWS) : nullptr;
            if (dst)
                asm volatile("red.global.add.f32 [%0], %1;"
                             :: "l"(dst), "f"(contrib) : "memory");
        }
    }
}

// ---------------------------------------------------------------------------
// Launch — TWO kernels
// inputs: 0=embeddings 1=W1 2=b1 3=W2 4=b2 5=W3 6=y 7=opt_length
// ---------------------------------------------------------------------------
extern "C" void kernel_launch(void* const* d_in, const int* in_sizes, int n_in,
                              void* d_out, int out_size) {
    const float* emb = (const float*)d_in[0];
    const float* W1  = (const float*)d_in[1];
    const float* b1  = (const float*)d_in[2];
    const float* W2  = (const float*)d_in[3];
    const float* b2  = (const float*)d_in[4];
    const float* W3  = (const float*)d_in[5];
    const int*   y   = (const int*)d_in[6];
    const void*  opt = (const void*)d_in[7];
    float* out = (float*)d_out;

    cudaFuncSetAttribute(layer1_kernel,
        cudaFuncAttributeMaxDynamicSharedMemorySize, SMEM_BYTES);
    cudaFuncSetAttribute(layer2_kernel,
        cudaFuncAttributeMaxDynamicSharedMemorySize, SMEM_BYTES);

    layer1_kernel<<<NCTA, 256, SMEM_BYTES>>>(emb, opt, b1, W1, out, out_size);
    layer2_kernel<<<NCTA, 256, SMEM_BYTES>>>(W2, b2, W3, y, out, out_size);
}

// round 14
// speedup vs baseline: 5.9695x; 5.9695x over previous
#include <cuda_runtime.h>
#include <math.h>

#define HID   1024
#define BSZ   16
#define NOPT  4
#define ROWS  (BSZ*NOPT)    // 64
#define TRUN  2
#define SEQ   1536
#define PLEN  512
#define QLEN  128

#define KSPLIT 32
#define KCHUNK (HID/KSPLIT)   // 32
#define NTILE  64

// Scratch (device globals — no allocation allowed)
__device__ float g_feats[ROWS*HID];
__device__ float g_h1[ROWS*HID];
__device__ float g_h2[ROWS*HID];

// ---------------------------------------------------------------------------
// PDL + f32x2 helpers
// ---------------------------------------------------------------------------
__device__ __forceinline__ void pdl_launch_dependents() {
    asm volatile("griddepcontrol.launch_dependents;");
}
__device__ __forceinline__ void pdl_wait() {
    asm volatile("griddepcontrol.wait;" ::: "memory");
}
__device__ __forceinline__ void fma_f32x2(unsigned long long& acc,
                                          unsigned long long a,
                                          unsigned long long b) {
    asm("fma.rn.f32x2 %0, %1, %2, %0;" : "+l"(acc) : "l"(a), "l"(b));
}
__device__ __forceinline__ float lo_f(unsigned long long v) {
    return __uint_as_float((unsigned)(v & 0xFFFFFFFFull));
}
__device__ __forceinline__ float hi_f(unsigned long long v) {
    return __uint_as_float((unsigned)(v >> 32));
}
__device__ __forceinline__ long long opt_at(const void* p, bool is64, int i) {
    if (is64) return ((const long long*)p)[i];
    return (long long)((const int*)p)[i];
}

// ---------------------------------------------------------------------------
// 1) prep (320 CTAs): blocks [0,256) bias-init h1/h2; blocks [256,320) feats.
//    Zeroes the loss output slot. Signals dependents immediately.
// ---------------------------------------------------------------------------
__global__ void __launch_bounds__(256)
prep_kernel(const float* __restrict__ emb, const void* __restrict__ opt_length,
            const float* __restrict__ b1, const float* __restrict__ b2,
            float* __restrict__ out, int out_size) {
    pdl_launch_dependents();   // let gemm0 start its W1 prologue now

    if (blockIdx.x == 0 && threadIdx.x == 0) {
        if (out_size == 1)             out[0] = 0.f;
        else if (out_size >= ROWS + 1) out[ROWS] = 0.f;
    }

    if (blockIdx.x < 256) {
        int i = blockIdx.x * 256 + threadIdx.x;     // 0..65535
        int j = i & (HID - 1);
        g_h1[i] = b1[j];
        g_h2[i] = b2[j];
        return;
    }
    int row = blockIdx.x - 256;      // b*NOPT + o
    int b = row >> 2, o = row & 3;

    bool is64 = (((const int*)opt_length)[1] == 0);
    long long cs = 0;
    for (int i = 0; i <= o; i++) cs += opt_at(opt_length, is64, i);
    int ohead = PLEN + QLEN + (int)cs;
    int otail = ohead + (int)opt_at(opt_length, is64, o + 1) - 1;
    int pos[6] = {0, PLEN - 1, PLEN, PLEN + QLEN - 1, ohead, otail};

    int h4 = threadIdx.x * 4;
    float4 acc = make_float4(0.f, 0.f, 0.f, 0.f);
    #pragma unroll
    for (int t = 0; t < TRUN; t++) {
        const float* base = emb + (size_t)(t * BSZ + b) * SEQ * HID;
        #pragma unroll
        for (int p = 0; p < 6; p++) {
            float4 v = *(const float4*)(base + (size_t)pos[p] * HID + h4);
            acc.x += v.x; acc.y += v.y; acc.z += v.z; acc.w += v.w;
        }
    }
    const float s = 0.25f;
    *(float4*)(g_feats + (size_t)row * HID + h4) =
        make_float4(acc.x * s, acc.y * s, acc.z * s, acc.w * s);
}

// ---------------------------------------------------------------------------
// 2) Split-K GEMM (R12 inner loop; R4 geometry): 64x64 tile, K-chunk 32,
//    grid (16,32)=512 CTAs, 256 thr, dup-A smem -> 11 inst/k, REDG.v4 epi.
//    PDL: W tile loaded BEFORE griddepcontrol.wait; A loaded after.
// ---------------------------------------------------------------------------
template <int LAYER>
__global__ void __launch_bounds__(256, 4)
gemm_kernel(const float* __restrict__ W) {
    __shared__ float2 As2[KCHUNK][66];   // [k][row] duplicated (a,a), pad 2
    __shared__ float  Ws[KCHUNK][64];    // [k][col]

    const float* A  = (LAYER == 0) ? g_feats : g_h1;
    float*      out = (LAYER == 0) ? g_h1    : g_h2;

    const int n0  = blockIdx.x * NTILE;
    const int k0  = blockIdx.y * KCHUNK;
    const int tid = threadIdx.x;

    // --- PDL prologue: W tile (independent of predecessor) ---
    {
        int c4 = (tid & 15) * 4;
        int kk = tid >> 4;
        #pragma unroll
        for (int i = 0; i < 2; i++) {
            int k = kk + i * 16;
            *(float4*)&Ws[k][c4] =
                *(const float4*)(W + (size_t)(k0 + k) * HID + n0 + c4);
        }
    }
    pdl_launch_dependents();   // successor may start its own prologue
    pdl_wait();                // predecessor's writes now visible

    // --- A tile (dependent), duplicated-transposed ---
    {
        int kk4 = (tid & 7) * 4;      // 0..28
        int r   = tid >> 3;           // 0..31
        #pragma unroll
        for (int rr = 0; rr < 2; rr++) {
            int row = r + rr * 32;
            float4 v = *(const float4*)(A + (size_t)row * HID + k0 + kk4);
            if (LAYER == 1) {
                v.x = fmaxf(v.x, 0.f); v.y = fmaxf(v.y, 0.f);
                v.z = fmaxf(v.z, 0.f); v.w = fmaxf(v.w, 0.f);
            }
            As2[kk4 + 0][row] = make_float2(v.x, v.x);
            As2[kk4 + 1][row] = make_float2(v.y, v.y);
            As2[kk4 + 2][row] = make_float2(v.z, v.z);
            As2[kk4 + 3][row] = make_float2(v.w, v.w);
        }
    }
    __syncthreads();

    const int c0 = (tid & 15) * 4;
    const int r0 = (tid >> 4) * 4;

    unsigned long long acc[4][2] = {};
    #pragma unroll
    for (int kk = 0; kk < KCHUNK; kk++) {
        ulonglong2 wq  = *(const ulonglong2*)&Ws[kk][c0];       // 2 packed col-pairs
        ulonglong2 a01 = *(const ulonglong2*)&As2[kk][r0 + 0];  // rows r0,r0+1 dup
        ulonglong2 a23 = *(const ulonglong2*)&As2[kk][r0 + 2];  // rows r0+2,r0+3

        fma_f32x2(acc[0][0], a01.x, wq.x); fma_f32x2(acc[0][1], a01.x, wq.y);
        fma_f32x2(acc[1][0], a01.y, wq.x); fma_f32x2(acc[1][1], a01.y, wq.y);
        fma_f32x2(acc[2][0], a23.x, wq.x); fma_f32x2(acc[2][1], a23.x, wq.y);
        fma_f32x2(acc[3][0], a23.y, wq.x); fma_f32x2(acc[3][1], a23.y, wq.y);
    }

    #pragma unroll
    for (int i = 0; i < 4; i++) {
        float* p = out + (size_t)(r0 + i) * HID + n0 + c0;
        asm volatile("red.global.add.v4.f32 [%0], {%1, %2, %3, %4};"
                     :: "l"(p),
                        "f"(lo_f(acc[i][0])), "f"(hi_f(acc[i][0])),
                        "f"(lo_f(acc[i][1])), "f"(hi_f(acc[i][1])) : "memory");
    }
}

// ---------------------------------------------------------------------------
// 3) gemv+loss, batch-per-CTA (16 CTAs x 256 thr), sync-free loss red.add.
//    PDL: W3 fetched into regs BEFORE the wait.
// ---------------------------------------------------------------------------
__global__ void __launch_bounds__(256)
gemv_loss_kernel(const float* __restrict__ W3, const int* __restrict__ y,
                 float* __restrict__ out, int out_size) {
    __shared__ float red[8];
    __shared__ float lsh[NOPT];

    const int b    = blockIdx.x;        // batch 0..15
    const int tid  = threadIdx.x;
    const int o    = tid >> 6;          // option 0..3
    const int lane = tid & 63;

    // --- PDL prologue: W3 (independent) into registers ---
    float4 wv[4];
    #pragma unroll
    for (int i = 0; i < 4; i++)
        wv[i] = *(const float4*)(W3 + (lane + i * 64) * 4);

    pdl_wait();                // h2 now complete

    const float* h = g_h2 + (size_t)(b * NOPT + o) * HID;
    float s = 0.f;
    #pragma unroll
    for (int i = 0; i < 4; i++) {       // 64 lanes * 4 iters * float4 = 1024
        int k = (lane + i * 64) * 4;
        float4 hv = *(const float4*)(h + k);
        s += fmaxf(hv.x, 0.f) * wv[i].x + fmaxf(hv.y, 0.f) * wv[i].y
           + fmaxf(hv.z, 0.f) * wv[i].z + fmaxf(hv.w, 0.f) * wv[i].w;
    }
    #pragma unroll
    for (int off = 16; off; off >>= 1)
        s += __shfl_down_sync(0xFFFFFFFFu, s, off);
    if ((tid & 31) == 0) red[tid >> 5] = s;
    __syncthreads();

    if (tid < NOPT) lsh[tid] = red[2 * tid] + red[2 * tid + 1];
    __syncthreads();

    if (tid == 0) {
        float l0 = lsh[0], l1 = lsh[1], l2 = lsh[2], l3 = lsh[3];
        if (out_size >= ROWS) {
            out[b * NOPT + 0] = l0; out[b * NOPT + 1] = l1;
            out[b * NOPT + 2] = l2; out[b * NOPT + 3] = l3;
        }
        float m  = fmaxf(fmaxf(l0, l1), fmaxf(l2, l3));
        float se = expf(l0 - m) + expf(l1 - m) + expf(l2 - m) + expf(l3 - m);
        float lse = m + logf(se);
        int yy = y[b];
        float ly = (yy == 0) ? l0 : (yy == 1) ? l1 : (yy == 2) ? l2 : l3;
        float contrib = -(ly - lse) * (1.0f / (float)BSZ);

        float* dst = (out_size == 1) ? out
                   : (out_size >= ROWS + 1) ? (out + ROWS) : nullptr;
        if (dst)
            asm volatile("red.global.add.f32 [%0], %1;"
                         :: "l"(dst), "f"(contrib) : "memory");
    }
}

// ---------------------------------------------------------------------------
// Launch — 4 kernels; nodes 2-4 launched with PDL so each overlaps its
// prologue with its predecessor.
// inputs: 0=embeddings 1=W1 2=b1 3=W2 4=b2 5=W3 6=y 7=opt_length
// ---------------------------------------------------------------------------
template <typename F, typename... Args>
static void launch_pdl(F* func, dim3 grid, dim3 block, Args... args) {
    cudaLaunchConfig_t cfg = {};
    cfg.gridDim  = grid;
    cfg.blockDim = block;
    cfg.stream   = 0;
    cudaLaunchAttribute attr[1];
    attr[0].id = cudaLaunchAttributeProgrammaticStreamSerialization;
    attr[0].val.programmaticStreamSerializationAllowed = 1;
    cfg.attrs    = attr;
    cfg.numAttrs = 1;
    cudaLaunchKernelEx(&cfg, func, args...);
}

extern "C" void kernel_launch(void* const* d_in, const int* in_sizes, int n_in,
                              void* d_out, int out_size) {
    const float* emb = (const float*)d_in[0];
    const float* W1  = (const float*)d_in[1];
    const float* b1  = (const float*)d_in[2];
    const float* W2  = (const float*)d_in[3];
    const float* b2  = (const float*)d_in[4];
    const float* W3  = (const float*)d_in[5];
    const int*   y   = (const int*)d_in[6];
    const void*  opt = (const void*)d_in[7];
    float* out = (float*)d_out;

    prep_kernel<<<320, 256>>>(emb, opt, b1, b2, out, out_size);
    launch_pdl(gemm_kernel<0>, dim3(16, KSPLIT), dim3(256), W1);
    launch_pdl(gemm_kernel<1>, dim3(16, KSPLIT), dim3(256), W2);
    launch_pdl(gemv_loss_kernel, dim3(BSZ), dim3(256), W3, y, out, out_size);
}